// round 13
// baseline (speedup 1.0000x reference)
#include <cuda_runtime.h>

// PatchExtractor3d: out[b, c*27 + i*9 + j*3 + l, d, h, w] = xpad[b, c, d+i, h+j, w+l]
// x [2,3,32,128,128] fp32 -> out [2,81,32,128,128] fp32, pad=1, K=3.
//
// HYBRID v2 (properly sized): block = (b, c, i, d, hchunk). One input-plane
// slab feeds the same 32 h-rows of 9 contiguous output planes (j,l).
// Warp owns 4 rows: 6 front-batched LDG.128 (slab+halo), 36 streaming STG.128.
// Read amplification 27x -> 1.5x vs gather; grid=2304, occ ~50%.

static constexpr int B_  = 2;
static constexpr int C_  = 3;
static constexpr int D_  = 32;
static constexpr int H_  = 128;
static constexpr int W_  = 128;
static constexpr int COUT = C_ * 27;   // 81
static constexpr int ROWQ = W_ / 4;    // 32 float4 per row

template<int L>
__device__ __forceinline__ float4 shift_row(float4 cur, int lane) {
    if (L == 1) return cur;
    float4 r;
    if (L == 0) {                       // out[w] = in[w-1]
        const float pw = __shfl_up_sync(0xffffffffu, cur.w, 1);
        r.x = (lane == 0) ? 0.f : pw;
        r.y = cur.x; r.z = cur.y; r.w = cur.z;
    } else {                            // out[w] = in[w+1]
        const float nx = __shfl_down_sync(0xffffffffu, cur.x, 1);
        r.x = cur.y; r.y = cur.z; r.z = cur.w;
        r.w = (lane == 31) ? 0.f : nx;
    }
    return r;
}

// Store 4 sequential rows of one (J,L) plane from registers v[J..J+3].
template<int J, int L>
__device__ __forceinline__ void store_plane4(const float4* v,
                                             float4* __restrict__ p,
                                             int lane) {
    #pragma unroll
    for (int k = 0; k < 4; ++k)
        __stcs(p + (size_t)k * ROWQ, shift_row<L>(v[k + J], lane));
}

__global__ __launch_bounds__(256, 4)
void patch3d_hybrid2(const float* __restrict__ x, float* __restrict__ out) {
    const int d   = blockIdx.x;          // 0..31
    const int ci  = blockIdx.y;          // 0..8 : c*3 + i
    const int bz  = blockIdx.z;          // 0..7 : b*4 + hchunk
    const int c   = ci / 3;
    const int i   = ci - c * 3;
    const int b   = bz >> 2;
    const int hc  = bz & 3;
    const int din = d + i - 1;

    const int warp = threadIdx.x >> 5;
    const int lane = threadIdx.x & 31;
    const int h0   = hc * 32 + warp * 4;          // this warp's first row

    float4* const out4 = reinterpret_cast<float4*>(out);
    const size_t base0 = ((size_t)(b * COUT + c * 27 + i * 9) * D_ + d) * H_;
    float4* const pw0  = out4 + (base0 + h0) * ROWQ + lane;  // jl=0 plane
    const size_t PS = (size_t)D_ * H_ * ROWQ;                 // plane stride

    if ((unsigned)din >= (unsigned)D_) {
        // whole 9-plane group is padding -> zero-stream this warp's rows
        const float4 z = make_float4(0.f, 0.f, 0.f, 0.f);
        #pragma unroll
        for (int jl = 0; jl < 9; ++jl) {
            float4* p = pw0 + (size_t)jl * PS;
            #pragma unroll
            for (int k = 0; k < 4; ++k)
                __stcs(p + (size_t)k * ROWQ, z);
        }
        return;
    }

    // ---- load 4-row slab + halo: input rows hin = h0-1 .. h0+4 ----
    const float4* const xp =
        reinterpret_cast<const float4*>(x) +
        (((size_t)(b * C_ + c) * D_ + din) * H_) * ROWQ + lane;
    float4 v[6];
    #pragma unroll
    for (int k = 0; k < 6; ++k) {
        const int hin = h0 - 1 + k;
        v[k] = ((unsigned)hin < (unsigned)H_)
             ? __ldg(xp + (size_t)hin * ROWQ)
             : make_float4(0.f, 0.f, 0.f, 0.f);
    }

    // ---- store 9 planes x 4 sequential rows each ----
    store_plane4<0, 0>(v, pw0 + 0 * PS, lane);
    store_plane4<0, 1>(v, pw0 + 1 * PS, lane);
    store_plane4<0, 2>(v, pw0 + 2 * PS, lane);
    store_plane4<1, 0>(v, pw0 + 3 * PS, lane);
    store_plane4<1, 1>(v, pw0 + 4 * PS, lane);
    store_plane4<1, 2>(v, pw0 + 5 * PS, lane);
    store_plane4<2, 0>(v, pw0 + 6 * PS, lane);
    store_plane4<2, 1>(v, pw0 + 7 * PS, lane);
    store_plane4<2, 2>(v, pw0 + 8 * PS, lane);
}

extern "C" void kernel_launch(void* const* d_in, const int* in_sizes, int n_in,
                              void* d_out, int out_size) {
    const float* x = (const float*)d_in[0];
    float* out = (float*)d_out;
    (void)in_sizes; (void)n_in; (void)out_size;

    dim3 grid(D_, 9, 8);                // (32, 9, 8) = 2304 blocks, 256 thr
    patch3d_hybrid2<<<grid, 256>>>(x, out);
}

// round 14
// speedup vs baseline: 1.0457x; 1.0457x over previous
#include <cuda_runtime.h>

// PatchExtractor3d: out[b, c*27 + i*9 + j*3 + l, d, h, w] = xpad[b, c, d+i, h+j, w+l]
// x [2,3,32,128,128] fp32 -> out [2,81,32,128,128] fp32, pad=1, K=3.
//
// Best-known gather (R6) + consecutive-row warp mapping: block = one (b,co,d)
// plane; each warp owns 16 CONSECUTIVE h-rows (8KB monotone load + store
// streams), 16 front-batched LDG.128 (MLP=16), then 16 shfl+STG.128.

static constexpr int B_  = 2;
static constexpr int C_  = 3;
static constexpr int D_  = 32;
static constexpr int H_  = 128;
static constexpr int W_  = 128;
static constexpr int COUT = C_ * 27;   // 81
static constexpr int ROWQ = W_ / 4;    // 32 float4 per row

template<int L>
__device__ __forceinline__ float4 shift_row(float4 cur, int lane) {
    if (L == 1) return cur;
    float4 r;
    if (L == 0) {                       // out[w] = in[w-1]
        const float pw = __shfl_up_sync(0xffffffffu, cur.w, 1);
        r.x = (lane == 0) ? 0.f : pw;
        r.y = cur.x; r.z = cur.y; r.w = cur.z;
    } else {                            // out[w] = in[w+1]
        const float nx = __shfl_down_sync(0xffffffffu, cur.x, 1);
        r.x = cur.y; r.y = cur.z; r.z = cur.w;
        r.w = (lane == 31) ? 0.f : nx;
    }
    return r;
}

template<int L>
__device__ __forceinline__ void do_plane(const float* __restrict__ xplane,
                                         float4* __restrict__ o4 /* row h0 */,
                                         int h0, int lane, int j) {
    float4 v[16];
    // Phase 1: 16 front-batched independent loads, consecutive input rows
    #pragma unroll
    for (int k = 0; k < 16; ++k) {
        const int hin = h0 + k + j - 1;
        if ((unsigned)hin < (unsigned)H_) {
            const float4* p =
                reinterpret_cast<const float4*>(xplane + (size_t)hin * W_) + lane;
            v[k] = __ldg(p);
        } else {
            v[k] = make_float4(0.f, 0.f, 0.f, 0.f);
        }
    }
    // Phase 2: shift + streaming stores, 16 consecutive output rows (8KB run)
    #pragma unroll
    for (int k = 0; k < 16; ++k)
        __stcs(o4 + (size_t)k * ROWQ, shift_row<L>(v[k], lane));
}

__global__ __launch_bounds__(256, 3)
void patch3d_kernel(const float* __restrict__ x, float* __restrict__ out) {
    const int d    = blockIdx.x;       // 0..31
    const int co   = blockIdx.y;       // 0..80
    const int b    = blockIdx.z;       // 0..1
    const int warp = threadIdx.x >> 5;
    const int lane = threadIdx.x & 31;
    const int h0   = warp * 16;        // 16 consecutive rows per warp

    // Block-uniform decomposition
    const int c   = co / 27;
    const int rem = co - c * 27;
    const int i   = rem / 9;
    const int jl  = rem - i * 9;
    const int j   = jl / 3;
    const int l   = jl - j * 3;
    const int din = d + i - 1;

    float4* const o4 = reinterpret_cast<float4*>(out)
        + ((size_t)((b * COUT + co) * D_ + d) * H_ + h0) * ROWQ + lane;

    if ((unsigned)din >= (unsigned)D_) {
        // whole plane is padding -> contiguous zero-store run
        const float4 z = make_float4(0.f, 0.f, 0.f, 0.f);
        #pragma unroll
        for (int k = 0; k < 16; ++k)
            __stcs(o4 + (size_t)k * ROWQ, z);
        return;
    }

    const float* xplane = x + (((size_t)(b * C_ + c) * D_ + din) * H_) * W_;

    if (l == 0)      do_plane<0>(xplane, o4, h0, lane, j);
    else if (l == 1) do_plane<1>(xplane, o4, h0, lane, j);
    else             do_plane<2>(xplane, o4, h0, lane, j);
}

extern "C" void kernel_launch(void* const* d_in, const int* in_sizes, int n_in,
                              void* d_out, int out_size) {
    const float* x = (const float*)d_in[0];
    float* out = (float*)d_out;
    (void)in_sizes; (void)n_in; (void)out_size;

    dim3 grid(D_, COUT, B_);           // (32, 81, 2) = 5184 blocks
    patch3d_kernel<<<grid, 256>>>(x, out);
}